// round 5
// baseline (speedup 1.0000x reference)
#include <cuda_runtime.h>
#include <cstdint>

// ---------------- problem constants ----------------
#define NB 4
#define NC 512
#define NG 2048
#define CH 3
#define OC 64
#define NBAS 10
#define NPT 8192
#define EPSV 1e-6f
#define BN_EPS 1e-5f

// output layout (float32, concatenated in return order)
#define OFF_Y   0
#define OFF_NF  524288
#define OFF_FP  598016
#define OFF_NH1 671744
#define OFF_H0  745472

// scratch (device globals). SoA: [chan][b*NG+g]
__device__ float g_pos[9 * NPT];
__device__ float g_conv[9 * NPT];
__device__ unsigned long long g_isum[9];
__device__ unsigned long long g_isq[9];

#define S_SUM 1.7179869184e10   // 2^34
#define S_SQ  2.68435456e8      // 2^28

__device__ __forceinline__ float ex2f(float x) {
    float y;
    asm("ex2.approx.ftz.f32 %0, %1;" : "=f"(y) : "f"(x));
    return y;
}

// exp2 on the FMA/ALU pipes only (no MUFU). x <= 0 expected.
// magic-number round-to-nearest-int + degree-5 Taylor + exponent splice.
__device__ __forceinline__ float pexp2(float x) {
    x = fmaxf(x, -126.0f);
    float r  = __fadd_rn(x, 12582912.0f);           // 1.5*2^23: RN to int
    float fi = __fadd_rn(r, -12582912.0f);
    float f  = __fadd_rn(x, -fi);                   // f in [-0.5, 0.5]
    float p;
    p = fmaf(0.0013333558f, f, 0.0096181291f);
    p = fmaf(p, f, 0.0555041087f);
    p = fmaf(p, f, 0.2402265069f);
    p = fmaf(p, f, 0.69314718056f);
    p = fmaf(p, f, 1.0f);
    unsigned t = (unsigned)__float_as_int(r);
    float s = __uint_as_float((t << 23) + 0x3F800000u);
    return p * s;
}

// ============================================================
// Kernel 1: RBF sums + fourier prior. MUFU/FMA pipe-balanced:
//           5 of 9 exps on MUFU (ex2), 4 on FMA pipe (pexp2).
// ============================================================
__global__ void __launch_bounds__(256)
k1_rbf(const float* __restrict__ xc, const float* __restrict__ yc,
       const float* __restrict__ xg, const float* __restrict__ sigma,
       const float* __restrict__ mu, const float* __restrict__ eps1,
       const float* __restrict__ bu, const float* __restrict__ rw,
       float* __restrict__ out)
{
    __shared__ float sdat[NC * 8];
    __shared__ float ssw[NBAS * 3];
    __shared__ float ssb[NBAS * 3];
    __shared__ float srw[NBAS];
    __shared__ float scoef[3];

    const int b = blockIdx.y;
    const int tid = threadIdx.x;

    // zero the deterministic fixed-point BN accumulators (one block only)
    if (blockIdx.x == 0 && b == 0 && tid < 9) {
        g_isum[tid] = 0ull;
        g_isq[tid] = 0ull;
    }

    for (int idx = tid; idx < NC * CH; idx += 256) {
        int n = idx / 3, c = idx - n * 3;
        int sw = n & 4;
        sdat[n * 8 + sw + c]        = xc[(b * NC + n) * 3 + c];
        sdat[n * 8 + (sw ^ 4) + c]  = yc[(b * NC + n) * 3 + c];
    }
    if (tid < NBAS * 3) {
        int k = tid / 3, p = tid - k * 3;
        float w_std = 1.0f / (expf(sigma[p]) + EPSV);
        ssw[tid] = expf(mu[p]) + w_std * eps1[(b * NBAS + k) * 3 + p];
        ssb[tid] = 6.283185307179586f * bu[(b * NBAS + k) * 3 + p];
    }
    if (tid >= 32 && tid < 32 + NBAS) srw[tid - 32] = rw[tid - 32];
    if (tid >= 64 && tid < 67) {
        int p = tid - 64;
        float inv = 1.0f / (expf(sigma[p]) + EPSV);
        scoef[p] = -0.5f * inv * inv * 1.4426950408889634f;
    }
    __syncthreads();

    const int wid = tid >> 5, lane = tid & 31;
    const int g = blockIdx.x * 8 + wid;
    const float* xgp = &xg[(b * NG + g) * 3];
    const float xg0 = xgp[0], xg1 = xgp[1], xg2 = xgp[2];
    const float c0 = scoef[0], c1 = scoef[1], c2 = scoef[2];

    float h0[9], h1[9];
#pragma unroll
    for (int j = 0; j < 9; j++) { h0[j] = 0.f; h1[j] = 0.f; }

#pragma unroll 4
    for (int it = 0; it < NC / 32; ++it) {
        int n = it * 32 + lane;
        int sw = n & 4;
        float4 v = *reinterpret_cast<const float4*>(&sdat[n * 8 + sw]);
        float4 u = *reinterpret_cast<const float4*>(&sdat[n * 8 + (sw ^ 4)]);
        float d0 = v.x - xg0, d1 = v.y - xg1, d2 = v.z - xg2;
        float s0 = d0 * d0, s1 = d1 * d1, s2 = d2 * d2;
        float e;
        // MUFU exps (5)
        e = ex2f(s0 * c0);  h0[0] += e; h1[0] = fmaf(e, u.x, h1[0]);
        e = ex2f(s0 * c2);  h0[2] += e; h1[2] = fmaf(e, u.x, h1[2]);
        e = ex2f(s1 * c1);  h0[4] += e; h1[4] = fmaf(e, u.y, h1[4]);
        e = ex2f(s2 * c0);  h0[6] += e; h1[6] = fmaf(e, u.z, h1[6]);
        e = ex2f(s2 * c2);  h0[8] += e; h1[8] = fmaf(e, u.z, h1[8]);
        // FMA-pipe exps (4)
        e = pexp2(s0 * c1); h0[1] += e; h1[1] = fmaf(e, u.x, h1[1]);
        e = pexp2(s1 * c0); h0[3] += e; h1[3] = fmaf(e, u.y, h1[3]);
        e = pexp2(s1 * c2); h0[5] += e; h1[5] = fmaf(e, u.y, h1[5]);
        e = pexp2(s2 * c1); h0[7] += e; h1[7] = fmaf(e, u.z, h1[7]);
    }

#pragma unroll
    for (int off = 16; off > 0; off >>= 1) {
#pragma unroll
        for (int j = 0; j < 9; j++) {
            h0[j] += __shfl_xor_sync(0xffffffffu, h0[j], off);
            h1[j] += __shfl_xor_sync(0xffffffffu, h1[j], off);
        }
    }

    if (lane < 9) {
        float h0v = 0.f, h1v = 0.f;
        switch (lane) {
            case 0: h0v = h0[0]; h1v = h1[0]; break;
            case 1: h0v = h0[1]; h1v = h1[1]; break;
            case 2: h0v = h0[2]; h1v = h1[2]; break;
            case 3: h0v = h0[3]; h1v = h1[3]; break;
            case 4: h0v = h0[4]; h1v = h1[4]; break;
            case 5: h0v = h0[5]; h1v = h1[5]; break;
            case 6: h0v = h0[6]; h1v = h1[6]; break;
            case 7: h0v = h0[7]; h1v = h1[7]; break;
            case 8: h0v = h0[8]; h1v = h1[8]; break;
        }
        int c = lane / 3;
        int p = lane - c * 3;
        float xgc = (c == 0) ? xg0 : ((c == 1) ? xg1 : xg2);
        float nh1 = h1v / (h0v + EPSV);

        float fp = 0.f;
#pragma unroll
        for (int k = 0; k < NBAS; k++) {
            float arg = __fadd_rn(__fmul_rn(ssw[k * 3 + p], xgc), ssb[k * 3 + p]);
            fp += srw[k] * cosf(arg);
        }
        fp *= 0.4472135954999579f;

        int pt = b * NG + g;
        int base = pt * 9 + lane;
        out[OFF_H0 + base] = h0v;
        out[OFF_NH1 + base] = nh1;
        out[OFF_FP + base] = fp;
        g_pos[lane * NPT + pt] = nh1 + fp;
    }
}

// ============================================================
// Kernel 2: depthwise convs + deterministic BN partial sums.
//           144 blocks x 512 (each block = one channel slice).
//           Per-block fp64 tree sums -> int64 fixed-point atomics.
// ============================================================
__global__ void __launch_bounds__(512)
k2_conv(const float* __restrict__ w1, const float* __restrict__ b1,
        const float* __restrict__ w2, const float* __restrict__ b2,
        const float* __restrict__ w3, const float* __restrict__ b3)
{
    __shared__ double ss[512], sq[512];
    const int tid = threadIdx.x;
    const int t = blockIdx.x * 512 + tid;            // < 73728
    const int chan = blockIdx.x >> 4;                // 16 blocks per channel
    const int rem = t - chan * NPT;
    const int g = rem & (NG - 1);
    const int c = chan / 3, p = chan - c * 3;

    const int ksz = (p == 0) ? 3 : ((p == 1) ? 5 : 9);
    const int pad = ksz >> 1;
    const float* w  = (p == 0) ? w1 : ((p == 1) ? w2 : w3);
    const float* bb = (p == 0) ? b1 : ((p == 1) ? b2 : b3);

    float acc = bb[c];
    const float* src = &g_pos[t - g];
    for (int tt = 0; tt < ksz; tt++) {
        int gg = g + tt - pad;
        if (gg >= 0 && gg < NG)
            acc = fmaf(src[gg], w[c * ksz + tt], acc);
    }
    g_conv[t] = acc;

    double v = (double)acc;
    ss[tid] = v;
    sq[tid] = v * v;
    __syncthreads();
    for (int off = 256; off > 0; off >>= 1) {
        if (tid < off) { ss[tid] += ss[tid + off]; sq[tid] += sq[tid + off]; }
        __syncthreads();
    }
    if (tid == 0) {
        long long is = __double2ll_rn(ss[0] * S_SUM);
        long long iq = __double2ll_rn(sq[0] * S_SQ);
        atomicAdd(&g_isum[chan], (unsigned long long)is);
        atomicAdd(&g_isq[chan],  (unsigned long long)iq);
    }
}

// ============================================================
// Kernel 3: stats finalize + BN apply + n_f + linear head.
//           256 blocks x 256, 32 points per block.
// ============================================================
__global__ void __launch_bounds__(256)
k3_head(const float* __restrict__ gamma, const float* __restrict__ beta,
        const float* __restrict__ gw, const float* __restrict__ gb,
        float* __restrict__ out)
{
    __shared__ float sfeat[32 * 19];
    __shared__ float swT[18 * 64];
    __shared__ float sbias[OC];
    __shared__ float sstat[18];
    __shared__ float sgam[9], sbet[9];

    const int tid = threadIdx.x;
    const int base = blockIdx.x * 32;

    for (int idx = tid; idx < OC * 18; idx += 256) {
        int o = idx / 18, k = idx - o * 18;
        swT[k * 64 + o] = gw[idx];
    }
    if (tid < OC) sbias[tid] = gb[tid];
    if (tid >= 96 && tid < 105) {
        int j = tid - 96;
        int c = j / 3, p = j - c * 3;
        sgam[j] = gamma[p * 3 + c];
        sbet[j] = beta[p * 3 + c];
    }
    if (tid >= 64 && tid < 73) {
        int j = tid - 64;
        double m  = (double)(long long)g_isum[j] * (1.0 / S_SUM) * (1.0 / 8192.0);
        double eq = (double)(long long)g_isq[j]  * (1.0 / S_SQ)  * (1.0 / 8192.0);
        double var = eq - m * m;
        if (var < 0.0) var = 0.0;
        sstat[j] = (float)m;
        sstat[9 + j] = (float)(1.0 / sqrt(var + (double)BN_EPS));
    }
    __syncthreads();

    for (int idx = tid; idx < 288; idx += 256)
        sfeat[(idx / 9) * 19 + (idx % 9)] = out[OFF_H0 + base * 9 + idx];
    for (int idx = tid; idx < 288; idx += 256) {
        int j = idx >> 5, t = idx & 31;
        float x = g_conv[j * NPT + base + t];
        sfeat[t * 19 + 9 + j] = sgam[j] * (x - sstat[j]) * sstat[9 + j] + sbet[j];
    }
    __syncthreads();

    for (int idx = tid; idx < 288; idx += 256)
        out[OFF_NF + base * 9 + idx] = sfeat[(idx / 9) * 19 + 9 + (idx % 9)];

    const int pt = tid >> 3;
    const int og = (tid & 7) * 8;
    const float* f = &sfeat[pt * 19];
    float acc[8];
#pragma unroll
    for (int oi = 0; oi < 8; oi++) acc[oi] = sbias[og + oi];
#pragma unroll
    for (int k = 0; k < 18; k++) {
        float fv = f[k];
        float4 wa = *reinterpret_cast<const float4*>(&swT[k * 64 + og]);
        float4 wb = *reinterpret_cast<const float4*>(&swT[k * 64 + og + 4]);
        acc[0] = fmaf(fv, wa.x, acc[0]);
        acc[1] = fmaf(fv, wa.y, acc[1]);
        acc[2] = fmaf(fv, wa.z, acc[2]);
        acc[3] = fmaf(fv, wa.w, acc[3]);
        acc[4] = fmaf(fv, wb.x, acc[4]);
        acc[5] = fmaf(fv, wb.y, acc[5]);
        acc[6] = fmaf(fv, wb.z, acc[6]);
        acc[7] = fmaf(fv, wb.w, acc[7]);
    }
    float* yo = &out[OFF_Y + (base + pt) * OC + og];
    *reinterpret_cast<float4*>(yo)     = make_float4(acc[0], acc[1], acc[2], acc[3]);
    *reinterpret_cast<float4*>(yo + 4) = make_float4(acc[4], acc[5], acc[6], acc[7]);
}

// ============================================================
extern "C" void kernel_launch(void* const* d_in, const int* in_sizes, int n_in,
                              void* d_out, int out_size)
{
    const float* xc    = (const float*)d_in[0];
    const float* yc    = (const float*)d_in[1];
    const float* xg    = (const float*)d_in[2];
    const float* sigma = (const float*)d_in[3];
    const float* mu    = (const float*)d_in[4];
    const float* eps1  = (const float*)d_in[5];
    const float* bu    = (const float*)d_in[6];
    const float* rw    = (const float*)d_in[7];
    const float* w1    = (const float*)d_in[8];
    const float* b1    = (const float*)d_in[9];
    const float* w2    = (const float*)d_in[10];
    const float* b2    = (const float*)d_in[11];
    const float* w3    = (const float*)d_in[12];
    const float* b3    = (const float*)d_in[13];
    const float* gamma = (const float*)d_in[14];
    const float* beta  = (const float*)d_in[15];
    const float* gw    = (const float*)d_in[16];
    const float* gb    = (const float*)d_in[17];
    float* out = (float*)d_out;

    dim3 grid1(NG / 8, NB);
    k1_rbf<<<grid1, 256>>>(xc, yc, xg, sigma, mu, eps1, bu, rw, out);
    k2_conv<<<144, 512>>>(w1, b1, w2, b2, w3, b3);
    k3_head<<<256, 256>>>(gamma, beta, gw, gb, out);
}

// round 7
// speedup vs baseline: 1.0635x; 1.0635x over previous
#include <cuda_runtime.h>
#include <cstdint>

// ---------------- problem constants ----------------
#define NB 4
#define NC 512
#define NG 2048
#define CH 3
#define OC 64
#define NBAS 10
#define NPT 8192
#define EPSV 1e-6f
#define BN_EPS 1e-5f

// output layout (float32, concatenated in return order)
#define OFF_Y   0
#define OFF_NF  524288
#define OFF_FP  598016
#define OFF_NH1 671744
#define OFF_H0  745472

// scratch (device globals). SoA: [chan][b*NG+g]
__device__ float g_pos[9 * NPT];
__device__ float g_conv[9 * NPT];
__device__ unsigned long long g_isum[9];
__device__ unsigned long long g_isq[9];

#define S_SUM 1.7179869184e10   // 2^34
#define S_SQ  2.68435456e8      // 2^28

__device__ __forceinline__ float ex2f(float x) {
    float y;
    asm("ex2.approx.ftz.f32 %0, %1;" : "=f"(y) : "f"(x));
    return y;
}

// exp2 on the FMA/ALU pipes only (no MUFU). x <= 0 expected.
// CORRECT range reduction (R4/R5-proven): fi = r - magic is exact,
// f = x - fi keeps full fraction precision. (The "compact" x-r form
// quantizes f to integers -- ulp(1.25e7)=1 -- and broke R6.)
__device__ __forceinline__ float pexp2(float x) {
    x = fmaxf(x, -126.0f);
    float r  = __fadd_rn(x, 12582912.0f);           // 1.5*2^23: RN to int
    float fi = __fadd_rn(r, -12582912.0f);          // exact integer part
    float f  = __fadd_rn(x, -fi);                   // f in [-0.5, 0.5]
    float p;
    p = fmaf(0.0013333558f, f, 0.0096181291f);
    p = fmaf(p, f, 0.0555041087f);
    p = fmaf(p, f, 0.2402265069f);
    p = fmaf(p, f, 0.69314718056f);
    p = fmaf(p, f, 1.0f);
    // bits(r) low 9 bits == n mod 512; splice to 2^n via IMAD
    unsigned t = (unsigned)__float_as_int(r);
    float s = __uint_as_float(t * 0x800000u + 0x3F800000u);
    return p * s;
}

// ============================================================
// Kernel 1: RBF sums + fourier prior. Issue/MUFU balanced:
//           7 of 9 exps on MUFU (ex2), 2 on FMA pipe (pexp2).
// ============================================================
__global__ void __launch_bounds__(256)
k1_rbf(const float* __restrict__ xc, const float* __restrict__ yc,
       const float* __restrict__ xg, const float* __restrict__ sigma,
       const float* __restrict__ mu, const float* __restrict__ eps1,
       const float* __restrict__ bu, const float* __restrict__ rw,
       float* __restrict__ out)
{
    __shared__ float sdat[NC * 8];
    __shared__ float ssw[NBAS * 3];
    __shared__ float ssb[NBAS * 3];
    __shared__ float srw[NBAS];
    __shared__ float scoef[3];

    const int b = blockIdx.y;
    const int tid = threadIdx.x;

    // zero the deterministic fixed-point BN accumulators (one block only)
    if (blockIdx.x == 0 && b == 0 && tid < 9) {
        g_isum[tid] = 0ull;
        g_isq[tid] = 0ull;
    }

    for (int idx = tid; idx < NC * CH; idx += 256) {
        int n = idx / 3, c = idx - n * 3;
        int sw = n & 4;
        sdat[n * 8 + sw + c]        = xc[(b * NC + n) * 3 + c];
        sdat[n * 8 + (sw ^ 4) + c]  = yc[(b * NC + n) * 3 + c];
    }
    if (tid < NBAS * 3) {
        int k = tid / 3, p = tid - k * 3;
        float w_std = 1.0f / (expf(sigma[p]) + EPSV);
        ssw[tid] = expf(mu[p]) + w_std * eps1[(b * NBAS + k) * 3 + p];
        ssb[tid] = 6.283185307179586f * bu[(b * NBAS + k) * 3 + p];
    }
    if (tid >= 32 && tid < 32 + NBAS) srw[tid - 32] = rw[tid - 32];
    if (tid >= 64 && tid < 67) {
        int p = tid - 64;
        float inv = 1.0f / (expf(sigma[p]) + EPSV);
        scoef[p] = -0.5f * inv * inv * 1.4426950408889634f;
    }
    __syncthreads();

    const int wid = tid >> 5, lane = tid & 31;
    const int g = blockIdx.x * 8 + wid;
    const float* xgp = &xg[(b * NG + g) * 3];
    const float xg0 = xgp[0], xg1 = xgp[1], xg2 = xgp[2];
    const float c0 = scoef[0], c1 = scoef[1], c2 = scoef[2];

    float h0[9], h1[9];
#pragma unroll
    for (int j = 0; j < 9; j++) { h0[j] = 0.f; h1[j] = 0.f; }

#pragma unroll 4
    for (int it = 0; it < NC / 32; ++it) {
        int n = it * 32 + lane;
        int sw = n & 4;
        float4 v = *reinterpret_cast<const float4*>(&sdat[n * 8 + sw]);
        float4 u = *reinterpret_cast<const float4*>(&sdat[n * 8 + (sw ^ 4)]);
        float d0 = v.x - xg0, d1 = v.y - xg1, d2 = v.z - xg2;
        float s0 = d0 * d0, s1 = d1 * d1, s2 = d2 * d2;
        float e;
        // MUFU exps (7)
        e = ex2f(s0 * c0);  h0[0] += e; h1[0] = fmaf(e, u.x, h1[0]);
        e = ex2f(s0 * c2);  h0[2] += e; h1[2] = fmaf(e, u.x, h1[2]);
        e = ex2f(s1 * c0);  h0[3] += e; h1[3] = fmaf(e, u.y, h1[3]);
        e = ex2f(s1 * c1);  h0[4] += e; h1[4] = fmaf(e, u.y, h1[4]);
        e = ex2f(s2 * c0);  h0[6] += e; h1[6] = fmaf(e, u.z, h1[6]);
        e = ex2f(s2 * c1);  h0[7] += e; h1[7] = fmaf(e, u.z, h1[7]);
        e = ex2f(s2 * c2);  h0[8] += e; h1[8] = fmaf(e, u.z, h1[8]);
        // FMA-pipe exps (2)
        e = pexp2(s0 * c1); h0[1] += e; h1[1] = fmaf(e, u.x, h1[1]);
        e = pexp2(s1 * c2); h0[5] += e; h1[5] = fmaf(e, u.y, h1[5]);
    }

#pragma unroll
    for (int off = 16; off > 0; off >>= 1) {
#pragma unroll
        for (int j = 0; j < 9; j++) {
            h0[j] += __shfl_xor_sync(0xffffffffu, h0[j], off);
            h1[j] += __shfl_xor_sync(0xffffffffu, h1[j], off);
        }
    }

    if (lane < 9) {
        float h0v = 0.f, h1v = 0.f;
        switch (lane) {
            case 0: h0v = h0[0]; h1v = h1[0]; break;
            case 1: h0v = h0[1]; h1v = h1[1]; break;
            case 2: h0v = h0[2]; h1v = h1[2]; break;
            case 3: h0v = h0[3]; h1v = h1[3]; break;
            case 4: h0v = h0[4]; h1v = h1[4]; break;
            case 5: h0v = h0[5]; h1v = h1[5]; break;
            case 6: h0v = h0[6]; h1v = h1[6]; break;
            case 7: h0v = h0[7]; h1v = h1[7]; break;
            case 8: h0v = h0[8]; h1v = h1[8]; break;
        }
        int c = lane / 3;
        int p = lane - c * 3;
        float xgc = (c == 0) ? xg0 : ((c == 1) ? xg1 : xg2);
        float nh1 = h1v / (h0v + EPSV);

        float fp = 0.f;
#pragma unroll
        for (int k = 0; k < NBAS; k++) {
            float arg = __fadd_rn(__fmul_rn(ssw[k * 3 + p], xgc), ssb[k * 3 + p]);
            fp += srw[k] * cosf(arg);
        }
        fp *= 0.4472135954999579f;

        int pt = b * NG + g;
        int base = pt * 9 + lane;
        out[OFF_H0 + base] = h0v;
        out[OFF_NH1 + base] = nh1;
        out[OFF_FP + base] = fp;
        g_pos[lane * NPT + pt] = nh1 + fp;
    }
}

// ============================================================
// Kernel 2: depthwise convs + deterministic BN partial sums.
//           144 blocks x 512 (each block = one channel slice).
//           Per-block fp64 tree sums -> int64 fixed-point atomics.
// ============================================================
__global__ void __launch_bounds__(512)
k2_conv(const float* __restrict__ w1, const float* __restrict__ b1,
        const float* __restrict__ w2, const float* __restrict__ b2,
        const float* __restrict__ w3, const float* __restrict__ b3)
{
    __shared__ double ss[512], sq[512];
    const int tid = threadIdx.x;
    const int t = blockIdx.x * 512 + tid;            // < 73728
    const int chan = blockIdx.x >> 4;                // 16 blocks per channel
    const int rem = t - chan * NPT;
    const int g = rem & (NG - 1);
    const int c = chan / 3, p = chan - c * 3;

    const int ksz = (p == 0) ? 3 : ((p == 1) ? 5 : 9);
    const int pad = ksz >> 1;
    const float* w  = (p == 0) ? w1 : ((p == 1) ? w2 : w3);
    const float* bb = (p == 0) ? b1 : ((p == 1) ? b2 : b3);

    float acc = bb[c];
    const float* src = &g_pos[t - g];
    for (int tt = 0; tt < ksz; tt++) {
        int gg = g + tt - pad;
        if (gg >= 0 && gg < NG)
            acc = fmaf(src[gg], w[c * ksz + tt], acc);
    }
    g_conv[t] = acc;

    double v = (double)acc;
    ss[tid] = v;
    sq[tid] = v * v;
    __syncthreads();
    for (int off = 256; off > 0; off >>= 1) {
        if (tid < off) { ss[tid] += ss[tid + off]; sq[tid] += sq[tid + off]; }
        __syncthreads();
    }
    if (tid == 0) {
        long long is = __double2ll_rn(ss[0] * S_SUM);
        long long iq = __double2ll_rn(sq[0] * S_SQ);
        atomicAdd(&g_isum[chan], (unsigned long long)is);
        atomicAdd(&g_isq[chan],  (unsigned long long)iq);
    }
}

// ============================================================
// Kernel 3: stats finalize + BN apply + n_f + linear head.
//           256 blocks x 256, 32 points per block.
// ============================================================
__global__ void __launch_bounds__(256)
k3_head(const float* __restrict__ gamma, const float* __restrict__ beta,
        const float* __restrict__ gw, const float* __restrict__ gb,
        float* __restrict__ out)
{
    __shared__ float sfeat[32 * 19];
    __shared__ float swT[18 * 64];
    __shared__ float sbias[OC];
    __shared__ float sstat[18];
    __shared__ float sgam[9], sbet[9];

    const int tid = threadIdx.x;
    const int base = blockIdx.x * 32;

    for (int idx = tid; idx < OC * 18; idx += 256) {
        int o = idx / 18, k = idx - o * 18;
        swT[k * 64 + o] = gw[idx];
    }
    if (tid < OC) sbias[tid] = gb[tid];
    if (tid >= 96 && tid < 105) {
        int j = tid - 96;
        int c = j / 3, p = j - c * 3;
        sgam[j] = gamma[p * 3 + c];
        sbet[j] = beta[p * 3 + c];
    }
    if (tid >= 64 && tid < 73) {
        int j = tid - 64;
        double m  = (double)(long long)g_isum[j] * (1.0 / S_SUM) * (1.0 / 8192.0);
        double eq = (double)(long long)g_isq[j]  * (1.0 / S_SQ)  * (1.0 / 8192.0);
        double var = eq - m * m;
        if (var < 0.0) var = 0.0;
        sstat[j] = (float)m;
        sstat[9 + j] = (float)(1.0 / sqrt(var + (double)BN_EPS));
    }
    __syncthreads();

    for (int idx = tid; idx < 288; idx += 256)
        sfeat[(idx / 9) * 19 + (idx % 9)] = out[OFF_H0 + base * 9 + idx];
    for (int idx = tid; idx < 288; idx += 256) {
        int j = idx >> 5, t = idx & 31;
        float x = g_conv[j * NPT + base + t];
        sfeat[t * 19 + 9 + j] = sgam[j] * (x - sstat[j]) * sstat[9 + j] + sbet[j];
    }
    __syncthreads();

    for (int idx = tid; idx < 288; idx += 256)
        out[OFF_NF + base * 9 + idx] = sfeat[(idx / 9) * 19 + 9 + (idx % 9)];

    const int pt = tid >> 3;
    const int og = (tid & 7) * 8;
    const float* f = &sfeat[pt * 19];
    float acc[8];
#pragma unroll
    for (int oi = 0; oi < 8; oi++) acc[oi] = sbias[og + oi];
#pragma unroll
    for (int k = 0; k < 18; k++) {
        float fv = f[k];
        float4 wa = *reinterpret_cast<const float4*>(&swT[k * 64 + og]);
        float4 wb = *reinterpret_cast<const float4*>(&swT[k * 64 + og + 4]);
        acc[0] = fmaf(fv, wa.x, acc[0]);
        acc[1] = fmaf(fv, wa.y, acc[1]);
        acc[2] = fmaf(fv, wa.z, acc[2]);
        acc[3] = fmaf(fv, wa.w, acc[3]);
        acc[4] = fmaf(fv, wb.x, acc[4]);
        acc[5] = fmaf(fv, wb.y, acc[5]);
        acc[6] = fmaf(fv, wb.z, acc[6]);
        acc[7] = fmaf(fv, wb.w, acc[7]);
    }
    float* yo = &out[OFF_Y + (base + pt) * OC + og];
    *reinterpret_cast<float4*>(yo)     = make_float4(acc[0], acc[1], acc[2], acc[3]);
    *reinterpret_cast<float4*>(yo + 4) = make_float4(acc[4], acc[5], acc[6], acc[7]);
}

// ============================================================
extern "C" void kernel_launch(void* const* d_in, const int* in_sizes, int n_in,
                              void* d_out, int out_size)
{
    const float* xc    = (const float*)d_in[0];
    const float* yc    = (const float*)d_in[1];
    const float* xg    = (const float*)d_in[2];
    const float* sigma = (const float*)d_in[3];
    const float* mu    = (const float*)d_in[4];
    const float* eps1  = (const float*)d_in[5];
    const float* bu    = (const float*)d_in[6];
    const float* rw    = (const float*)d_in[7];
    const float* w1    = (const float*)d_in[8];
    const float* b1    = (const float*)d_in[9];
    const float* w2    = (const float*)d_in[10];
    const float* b2    = (const float*)d_in[11];
    const float* w3    = (const float*)d_in[12];
    const float* b3    = (const float*)d_in[13];
    const float* gamma = (const float*)d_in[14];
    const float* beta  = (const float*)d_in[15];
    const float* gw    = (const float*)d_in[16];
    const float* gb    = (const float*)d_in[17];
    float* out = (float*)d_out;

    dim3 grid1(NG / 8, NB);
    k1_rbf<<<grid1, 256>>>(xc, yc, xg, sigma, mu, eps1, bu, rw, out);
    k2_conv<<<144, 512>>>(w1, b1, w2, b2, w3, b3);
    k3_head<<<256, 256>>>(gamma, beta, gw, gb, out);
}